// round 14
// baseline (speedup 1.0000x reference)
#include <cuda_runtime.h>
#include <cuda_fp16.h>
#include <math.h>
#include <stdint.h>

#define NN 20000
#define EE 160000
#define CC 1024

// ===================== helpers ==============================================
__device__ __forceinline__ uint32_t smem_to_u32(const void* p) {
    uint32_t a;
    asm("{ .reg .u64 t; cvta.to.shared.u64 t, %1; cvt.u32.u64 %0, t; }"
        : "=r"(a) : "l"(p));
    return a;
}

__device__ __forceinline__ uint32_t SWZ(uint32_t o) {
    return o ^ ((o >> 3) & 0x70);
}

__device__ __forceinline__ void ldsm4(uint32_t* r, uint32_t addr) {
    asm volatile("ldmatrix.sync.aligned.m8n8.x4.shared.b16 {%0,%1,%2,%3}, [%4];"
        : "=r"(r[0]), "=r"(r[1]), "=r"(r[2]), "=r"(r[3]) : "r"(addr));
}

__device__ __forceinline__ void mma_fp16(float* d, const uint32_t* a,
                                         const uint32_t* b) {
    asm volatile(
        "mma.sync.aligned.m16n8k16.row.col.f32.f16.f16.f32 "
        "{%0,%1,%2,%3},{%4,%5,%6,%7},{%8,%9},{%0,%1,%2,%3};"
        : "+f"(d[0]), "+f"(d[1]), "+f"(d[2]), "+f"(d[3])
        : "r"(a[0]), "r"(a[1]), "r"(a[2]), "r"(a[3]), "r"(b[0]), "r"(b[1]));
}

__device__ __forceinline__ void cpa16(uint32_t dst, const void* src, bool valid) {
    asm volatile("cp.async.cg.shared.global [%0], [%1], 16, %2;"
        :: "r"(dst), "l"(src), "r"(valid ? 16 : 0));
}
#define CP_COMMIT() asm volatile("cp.async.commit_group;" ::: "memory")
#define CP_WAIT(n)  asm volatile("cp.async.wait_group %0;" :: "n"(n) : "memory")

__device__ __forceinline__ float sigm(float x) { return 1.f / (1.f + expf(-x)); }

// ===================== scratch (__device__ globals) =========================
__device__ __align__(16) float g_deg[NN];
__device__ __align__(16) float g_dis[NN];
__device__ int   g_cnt[NN];
__device__ int   g_rp[NN + 1];
__device__ int   g_cur[NN];
__device__ int   g_col[EE];
__device__ __align__(16) float g_val[EE];

__device__ __align__(16) float g_T2h[(size_t)NN * CC];   // H*R fp32 (sub term)
__device__ __align__(16) float g_Zp[(size_t)NN * CC];    // Z (post-sigmoid)

// fp16 activation buffers
#define ABUF ((size_t)NN * CC)
__device__ __align__(16) __half g_hX[ABUF];
__device__ __align__(16) __half g_h1X[ABUF];
__device__ __align__(16) __half g_h2X[ABUF];
__device__ __align__(16) __half g_hH[ABUF];
__device__ __align__(16) __half g_h1H[ABUF];
__device__ __align__(16) __half g_h2H[ABUF];
__device__ __align__(16) __half g_hR[ABUF];
__device__ __align__(16) __half g_h1R[ABUF];
__device__ __align__(16) __half g_h2R[ABUF];

// transposed fp16 weights: 6 x [1024 n][3072 k]
#define WSZ ((size_t)1024 * 3072)
__device__ __align__(16) __half g_Wt[6 * WSZ];

// ===================== graph normalization + CSR build ======================
__global__ void k_zero() {
    int i = blockIdx.x * 256 + threadIdx.x;
    if (i < NN) { g_deg[i] = 0.0f; g_cnt[i] = 0; }
}

__global__ void k_deg(const int* __restrict__ src, const int* __restrict__ dst,
                      const float* __restrict__ ew) {
    int e = blockIdx.x * 256 + threadIdx.x;
    if (e < EE) {
        int s = src[e], d = dst[e];
        float w = (s == d) ? 0.0f : ew[e];
        atomicAdd(&g_deg[s], w);
        atomicAdd(&g_cnt[d], 1);
    }
}

__global__ void k_dis() {
    int i = blockIdx.x * 256 + threadIdx.x;
    if (i < NN) {
        float d = g_deg[i];
        g_dis[i] = (d > 0.0f) ? rsqrtf(d) : 0.0f;
    }
}

__global__ void k_scan() {
    __shared__ int wsum[32];
    __shared__ int sh_carry;
    int tid = threadIdx.x;
    int lane = tid & 31, wid = tid >> 5;
    if (tid == 0) sh_carry = 0;
    __syncthreads();
    for (int base = 0; base < NN; base += 1024) {
        int i = base + tid;
        int v = (i < NN) ? g_cnt[i] : 0;
        int inc = v;
#pragma unroll
        for (int off = 1; off < 32; off <<= 1) {
            int t = __shfl_up_sync(0xFFFFFFFFu, inc, off);
            if (lane >= off) inc += t;
        }
        if (lane == 31) wsum[wid] = inc;
        __syncthreads();
        if (wid == 0) {
            int wv = wsum[lane];
            int winc = wv;
#pragma unroll
            for (int off = 1; off < 32; off <<= 1) {
                int t = __shfl_up_sync(0xFFFFFFFFu, winc, off);
                if (lane >= off) winc += t;
            }
            wsum[lane] = winc - wv;
        }
        __syncthreads();
        int excl = sh_carry + wsum[wid] + inc - v;
        if (i < NN) { g_rp[i] = excl; g_cur[i] = excl; }
        __syncthreads();
        if (tid == 1023) sh_carry = excl + v;
        __syncthreads();
    }
    if (tid == 0) g_rp[NN] = sh_carry;
}

__global__ void k_fill(const int* __restrict__ src, const int* __restrict__ dst,
                       const float* __restrict__ ew) {
    int e = blockIdx.x * 256 + threadIdx.x;
    if (e < EE) {
        int s = src[e], d = dst[e];
        float w = (s == d) ? 0.0f : ew[e];
        float nw = -g_dis[s] * w * g_dis[d];
        int pos = atomicAdd(&g_cur[d], 1);
        g_col[pos] = s;
        g_val[pos] = nw;
    }
}

// ===================== converts =============================================
__global__ void k_cvtA(const float* __restrict__ in, __half* __restrict__ hi) {
    size_t i = (size_t)blockIdx.x * 256 + threadIdx.x;
    if (i < (size_t)NN * CC / 4) {
        float4 v = *(const float4*)(in + i * 4);
        __half2 h0 = __floats2half2_rn(v.x, v.y);
        __half2 h1 = __floats2half2_rn(v.z, v.w);
        *(uint2*)(hi + i * 4) = make_uint2(*(uint32_t*)&h0, *(uint32_t*)&h1);
    }
}

struct WPtrs { const float* w[6]; };
__global__ void k_cvtW(WPtrs wp, __half* __restrict__ wt) {
    __shared__ float ts[32][33];
    int kb = blockIdx.x * 32;
    int nb = blockIdx.y * 32;
    const float* W = wp.w[blockIdx.z];
    int c = threadIdx.x & 31, r8 = threadIdx.x >> 5;
#pragma unroll
    for (int i = 0; i < 4; i++) {
        int kr = r8 + i * 8;
        ts[kr][c] = W[(size_t)(kb + kr) * 1024 + nb + c];
    }
    __syncthreads();
    __half* bh = wt + (size_t)blockIdx.z * WSZ;
#pragma unroll
    for (int i = 0; i < 4; i++) {
        int nr = r8 + i * 8;
        bh[(size_t)(nb + nr) * 3072 + kb + c] = __float2half(ts[c][nr]);
    }
}

// ============ Laplacian apply: fp16 gather, fp32 accum, fp16 out ============
template <bool CHEB2>
__global__ void k_lap16(const __half* __restrict__ in,
                        const float* __restrict__ sub,
                        __half* __restrict__ out) {
    int node = blockIdx.x;
    int c4 = threadIdx.x;
    int s = g_rp[node], e = g_rp[node + 1];
    float a0 = 0.f, a1 = 0.f, a2 = 0.f, a3 = 0.f;
    for (int i = s; i < e; i++) {
        float w = __ldg(&g_val[i]);
        int   c = __ldg(&g_col[i]);
        uint2 hv = *(const uint2*)(in + (size_t)c * CC + c4 * 4);
        __half2 p0 = *reinterpret_cast<__half2*>(&hv.x);
        __half2 p1 = *reinterpret_cast<__half2*>(&hv.y);
        float2 f0 = __half22float2(p0);
        float2 f1 = __half22float2(p1);
        a0 += w * f0.x; a1 += w * f0.y; a2 += w * f1.x; a3 += w * f1.y;
    }
    if (CHEB2) {
        float4 sb = *(const float4*)(sub + (size_t)node * CC + c4 * 4);
        a0 = 2.f * a0 - sb.x; a1 = 2.f * a1 - sb.y;
        a2 = 2.f * a2 - sb.z; a3 = 2.f * a3 - sb.w;
    }
    __half2 o0 = __floats2half2_rn(a0, a1);
    __half2 o1 = __floats2half2_rn(a2, a3);
    *(uint2*)(out + (size_t)node * CC + c4 * 4) =
        make_uint2(*(uint32_t*)&o0, *(uint32_t*)&o1);
}

// ===================== merged pipelined MMA GEMM ============================
// CTA tile 128M x 128N, BK=64, 3-stage pipeline, 2 CTAs/SM.
#define STAGE 32768u
#define OFF_B  16384u
#define GEMM_SMEM (3 * 32768)

struct SegPtrsH { const __half* a[6]; };
struct GJob {
    const __half* Wa; const __half* Wb;
    float* C;
    const float* b1; const float* b2;
    int nseg; int epi;   // 1 Z, 2 R->H*R, 3 final mix
};
struct GParams {
    SegPtrsH sp;
    GJob job[2];
    const float* Hin; const float* Zin;
    __half* hr16; float* hr32;
    float* outp;
};

__global__ __launch_bounds__(256, 2)
void k_gemmM(GParams gp) {
    extern __shared__ __align__(1024) char sm[];
    const uint32_t smb = smem_to_u32(sm);
    const int tid = threadIdx.x;
    const int m0 = blockIdx.y * 128;
    const int n0 = blockIdx.x * 128;
    const GJob jb = gp.job[blockIdx.z];
    const int nst = jb.nseg * 16;

    const int warp = tid >> 5, lane = tid & 31;
    const int wm = (warp >> 1) * 32, wn = (warp & 1) * 64;
    const int lj = lane >> 3, lr = lane & 7;
    const uint32_t a_off = (uint32_t)(((lj & 1) * 8 + lr) * 128 + (lj >> 1) * 16);
    const uint32_t b_off = (uint32_t)(((lj >> 1) * 8 + lr) * 128 + (lj & 1) * 16);

    float acc[2][8][4];
#pragma unroll
    for (int a = 0; a < 2; a++)
#pragma unroll
        for (int b = 0; b < 8; b++)
#pragma unroll
            for (int c = 0; c < 4; c++) acc[a][b][c] = 0.f;

    auto issue = [&](int st) {
        const int seg = st >> 4;
        const int k0 = (st & 15) * 64;
        const int wk = (seg % 3) * 1024 + k0;
        const uint32_t buf = smb + (uint32_t)(st % 3) * STAGE;
        const __half* ah = gp.sp.a[seg];
        const __half* wt = (seg < 3) ? jb.Wa : jb.Wb;
#pragma unroll
        for (int t = 0; t < 4; t++) {
            int c = tid + t * 256;
            int row = c >> 3, cc = c & 7;
            bool v = (m0 + row) < NN;
            size_t g = (size_t)(m0 + row) * 1024 + k0 + cc * 8;
            cpa16(buf + SWZ((uint32_t)(row * 128 + cc * 16)), ah + g, v);
        }
#pragma unroll
        for (int t = 0; t < 4; t++) {
            int c = tid + t * 256;
            int row = c >> 3, cc = c & 7;
            size_t g = (size_t)(n0 + row) * 3072 + wk + cc * 8;
            cpa16(buf + OFF_B + SWZ((uint32_t)(row * 128 + cc * 16)), wt + g, true);
        }
    };

    issue(0);
    CP_COMMIT();
    issue(1);
    CP_COMMIT();

    for (int st = 0; st < nst; st++) {
        if (st + 2 < nst) {
            issue(st + 2);
            CP_COMMIT();
            CP_WAIT(2);
        } else if (st + 1 < nst) {
            CP_WAIT(1);
        } else {
            CP_WAIT(0);
        }
        __syncthreads();
        const uint32_t buf = smb + (uint32_t)(st % 3) * STAGE;

#pragma unroll
        for (int kk = 0; kk < 4; kk++) {
            const uint32_t kb = (uint32_t)(kk * 32);
            uint32_t ah[2][4];
#pragma unroll
            for (int mi = 0; mi < 2; mi++) {
                uint32_t ad = buf + SWZ((uint32_t)((wm + mi * 16) * 128) + kb + a_off);
                ldsm4(ah[mi], ad);
            }
#pragma unroll
            for (int g = 0; g < 4; g++) {
                uint32_t bd = buf + OFF_B +
                    SWZ((uint32_t)((wn + g * 16) * 128) + kb + b_off);
                uint32_t bh[4];
                ldsm4(bh, bd);
#pragma unroll
                for (int mi = 0; mi < 2; mi++) {
#pragma unroll
                    for (int f = 0; f < 2; f++)
                        mma_fp16(acc[mi][2 * g + f], ah[mi], bh + 2 * f);
                }
            }
        }
        __syncthreads();
    }

    // ---- fused epilogue ----
    const int gq = lane >> 2, tq = lane & 3;
    const int epi = jb.epi;
    float* C = jb.C;
#pragma unroll
    for (int mi = 0; mi < 2; mi++) {
#pragma unroll
        for (int hh = 0; hh < 2; hh++) {
            int r = m0 + wm + mi * 16 + gq + hh * 8;
            if (r >= NN) continue;
#pragma unroll
            for (int nf = 0; nf < 8; nf++) {
                int col = n0 + wn + nf * 8 + tq * 2;
                float v0 = acc[mi][nf][2 * hh];
                float v1 = acc[mi][nf][2 * hh + 1];
                size_t o = (size_t)r * 1024 + col;
                float2 b1 = *(const float2*)(jb.b1 + col);
                float2 b2 = *(const float2*)(jb.b2 + col);
                if (epi == 1) {
                    float z0 = sigm(v0 + b1.x + b2.x);
                    float z1 = sigm(v1 + b1.y + b2.y);
                    *(float2*)(C + o) = make_float2(z0, z1);
                } else if (epi == 2) {
                    float2 hv = *(const float2*)(gp.Hin + o);
                    float hr0 = hv.x * sigm(v0 + b1.x + b2.x);
                    float hr1 = hv.y * sigm(v1 + b1.y + b2.y);
                    *(float2*)(gp.hr32 + o) = make_float2(hr0, hr1);
                    __half2 h = __floats2half2_rn(hr0, hr1);
                    *(uint32_t*)(gp.hr16 + o) = *(uint32_t*)&h;
                } else {
                    // final: v already = Xcat@Wxh + HRcat@Whh
                    float2 zv = *(const float2*)(gp.Zin + o);
                    float2 hv = *(const float2*)(gp.Hin + o);
                    float t0 = tanhf(v0 + b1.x + b2.x);
                    float t1 = tanhf(v1 + b1.y + b2.y);
                    float o0 = zv.x * hv.x + (1.f - zv.x) * t0;
                    float o1 = zv.y * hv.y + (1.f - zv.y) * t1;
                    *(float2*)(gp.outp + o) = make_float2(o0, o1);
                }
            }
        }
    }
}

// ===================== launch ===============================================
extern "C" void kernel_launch(void* const* d_in, const int* in_sizes, int n_in,
                              void* d_out, int out_size) {
    const float* x   = (const float*)d_in[0];
    const float* H   = (const float*)d_in[1];
    const int*   ei  = (const int*)d_in[2];
    const int*   src = ei;
    const int*   dst = ei + EE;
    const float* ew  = (const float*)d_in[3];
    const float* Wxz = (const float*)d_in[4];
    const float* bxz = (const float*)d_in[5];
    const float* Whz = (const float*)d_in[6];
    const float* bhz = (const float*)d_in[7];
    const float* Wxr = (const float*)d_in[8];
    const float* bxr = (const float*)d_in[9];
    const float* Whr = (const float*)d_in[10];
    const float* bhr = (const float*)d_in[11];
    const float* Wxh = (const float*)d_in[12];
    const float* bxh = (const float*)d_in[13];
    const float* Whh = (const float*)d_in[14];
    const float* bhh = (const float*)d_in[15];
    float* out = (float*)d_out;

    float *T2h, *Zp;
    cudaGetSymbolAddress((void**)&T2h, g_T2h);
    cudaGetSymbolAddress((void**)&Zp,  g_Zp);

    __half *hX, *h1X, *h2X, *hH, *h1H, *h2H, *hR, *h1R, *h2R, *Wt;
    cudaGetSymbolAddress((void**)&hX,  g_hX);
    cudaGetSymbolAddress((void**)&h1X, g_h1X);
    cudaGetSymbolAddress((void**)&h2X, g_h2X);
    cudaGetSymbolAddress((void**)&hH,  g_hH);
    cudaGetSymbolAddress((void**)&h1H, g_h1H);
    cudaGetSymbolAddress((void**)&h2H, g_h2H);
    cudaGetSymbolAddress((void**)&hR,  g_hR);
    cudaGetSymbolAddress((void**)&h1R, g_h1R);
    cudaGetSymbolAddress((void**)&h2R, g_h2R);
    cudaGetSymbolAddress((void**)&Wt,  g_Wt);

    cudaFuncSetAttribute(k_gemmM,
        cudaFuncAttributeMaxDynamicSharedMemorySize, GEMM_SMEM);

    const int NB_N = (NN + 255) / 256;
    const int NB_E = (EE + 255) / 256;
    const int NB_F4 = (int)(((size_t)NN * CC / 4 + 255) / 256);
    const int MT = (NN + 127) / 128;         // 157 m-tiles

    // normalization + CSR
    k_zero<<<NB_N, 256>>>();
    k_deg <<<NB_E, 256>>>(src, dst, ew);
    k_dis <<<NB_N, 256>>>();
    k_scan<<<1, 1024>>>();
    k_fill<<<NB_E, 256>>>(src, dst, ew);

    // weight transpose + fp16 (order: Wxz, Whz, Wxr, Whr, Wxh, Whh)
    WPtrs wp;
    wp.w[0] = Wxz; wp.w[1] = Whz; wp.w[2] = Wxr;
    wp.w[3] = Whr; wp.w[4] = Wxh; wp.w[5] = Whh;
    k_cvtW<<<dim3(96, 32, 6), 256>>>(wp, Wt);

    // x, H fp16 converts
    k_cvtA<<<NB_F4, 256>>>(x, hX);
    k_cvtA<<<NB_F4, 256>>>(H, hH);

    // Chebyshev recursions (fp16 gather, fp32 accum, fp16 out)
    k_lap16<false><<<NN, 256>>>(hX,  nullptr, h1X);
    k_lap16<true> <<<NN, 256>>>(h1X, x,       h2X);
    k_lap16<false><<<NN, 256>>>(hH,  nullptr, h1H);
    k_lap16<true> <<<NN, 256>>>(h1H, H,       h2H);

    // merged Z / R GEMM (one launch, blockIdx.z = job; both 6-seg = balanced)
    GParams gzr;
    gzr.sp.a[0] = hX;  gzr.sp.a[1] = h1X; gzr.sp.a[2] = h2X;
    gzr.sp.a[3] = hH;  gzr.sp.a[4] = h1H; gzr.sp.a[5] = h2H;
    gzr.Hin = H; gzr.Zin = nullptr;
    gzr.hr16 = hR; gzr.hr32 = T2h; gzr.outp = nullptr;
    gzr.job[0] = {Wt, Wt + WSZ, Zp, bxz, bhz, 6, 1};                 // Z
    gzr.job[1] = {Wt + 2 * WSZ, Wt + 3 * WSZ, nullptr, bxr, bhr, 6, 2}; // R->HR
    k_gemmM<<<dim3(8, MT, 2), 256, GEMM_SMEM>>>(gzr);

    // Chebyshev recursion for H*R
    k_lap16<false><<<NN, 256>>>(hR,  nullptr, h1R);
    k_lap16<true> <<<NN, 256>>>(h1R, T2h,     h2R);

    // final 6-seg GEMM: out = Z*H + (1-Z)*tanh(Xcat@Wxh + HRcat@Whh + b)
    GParams gpf;
    gpf.sp.a[0] = hX;  gpf.sp.a[1] = h1X; gpf.sp.a[2] = h2X;
    gpf.sp.a[3] = hR;  gpf.sp.a[4] = h1R; gpf.sp.a[5] = h2R;
    gpf.Hin = H; gpf.Zin = Zp;
    gpf.hr16 = nullptr; gpf.hr32 = nullptr; gpf.outp = out;
    gpf.job[0] = {Wt + 4 * WSZ, Wt + 5 * WSZ, nullptr, bxh, bhh, 6, 3};
    gpf.job[1] = gpf.job[0];
    k_gemmM<<<dim3(8, MT, 1), 256, GEMM_SMEM>>>(gpf);
}

// round 15
// speedup vs baseline: 1.0110x; 1.0110x over previous
#include <cuda_runtime.h>
#include <cuda_fp16.h>
#include <math.h>
#include <stdint.h>

#define NN 20000
#define EE 160000
#define CC 1024

// ===================== helpers ==============================================
__device__ __forceinline__ uint32_t smem_to_u32(const void* p) {
    uint32_t a;
    asm("{ .reg .u64 t; cvta.to.shared.u64 t, %1; cvt.u32.u64 %0, t; }"
        : "=r"(a) : "l"(p));
    return a;
}

__device__ __forceinline__ uint32_t SWZ(uint32_t o) {
    return o ^ ((o >> 3) & 0x70);
}

__device__ __forceinline__ void ldsm4(uint32_t* r, uint32_t addr) {
    asm volatile("ldmatrix.sync.aligned.m8n8.x4.shared.b16 {%0,%1,%2,%3}, [%4];"
        : "=r"(r[0]), "=r"(r[1]), "=r"(r[2]), "=r"(r[3]) : "r"(addr));
}

__device__ __forceinline__ void mma_fp16(float* d, const uint32_t* a,
                                         const uint32_t* b) {
    asm volatile(
        "mma.sync.aligned.m16n8k16.row.col.f32.f16.f16.f32 "
        "{%0,%1,%2,%3},{%4,%5,%6,%7},{%8,%9},{%0,%1,%2,%3};"
        : "+f"(d[0]), "+f"(d[1]), "+f"(d[2]), "+f"(d[3])
        : "r"(a[0]), "r"(a[1]), "r"(a[2]), "r"(a[3]), "r"(b[0]), "r"(b[1]));
}

__device__ __forceinline__ void cpa16(uint32_t dst, const void* src, bool valid) {
    asm volatile("cp.async.cg.shared.global [%0], [%1], 16, %2;"
        :: "r"(dst), "l"(src), "r"(valid ? 16 : 0));
}
#define CP_COMMIT() asm volatile("cp.async.commit_group;" ::: "memory")
#define CP_WAIT(n)  asm volatile("cp.async.wait_group %0;" :: "n"(n) : "memory")

__device__ __forceinline__ float sigm(float x) { return 1.f / (1.f + expf(-x)); }

// ===================== scratch (__device__ globals) =========================
__device__ __align__(16) float g_deg[NN];
__device__ __align__(16) float g_dis[NN];
__device__ int   g_cnt[NN];
__device__ int   g_rp[NN + 1];
__device__ int   g_cur[NN];
__device__ int   g_col[EE];
__device__ __align__(16) float g_val[EE];

__device__ __align__(16) float g_T2h[(size_t)NN * CC];   // H*R fp32 (sub term)
__device__ __align__(16) float g_Zp[(size_t)NN * CC];    // Z (post-sigmoid)

// fp16 activation buffers
#define ABUF ((size_t)NN * CC)
__device__ __align__(16) __half g_hX[ABUF];
__device__ __align__(16) __half g_h1X[ABUF];
__device__ __align__(16) __half g_h2X[ABUF];
__device__ __align__(16) __half g_hH[ABUF];
__device__ __align__(16) __half g_h1H[ABUF];
__device__ __align__(16) __half g_h2H[ABUF];
__device__ __align__(16) __half g_hR[ABUF];
__device__ __align__(16) __half g_h1R[ABUF];
__device__ __align__(16) __half g_h2R[ABUF];

// transposed fp16 weights: 6 x [1024 n][3072 k]
#define WSZ ((size_t)1024 * 3072)
__device__ __align__(16) __half g_Wt[6 * WSZ];

// ===================== graph normalization + CSR build ======================
__global__ void k_zero() {
    int i = blockIdx.x * 256 + threadIdx.x;
    if (i < NN) { g_deg[i] = 0.0f; g_cnt[i] = 0; }
}

__global__ void k_deg(const int* __restrict__ src, const int* __restrict__ dst,
                      const float* __restrict__ ew) {
    int e = blockIdx.x * 256 + threadIdx.x;
    if (e < EE) {
        int s = src[e], d = dst[e];
        float w = (s == d) ? 0.0f : ew[e];
        atomicAdd(&g_deg[s], w);
        atomicAdd(&g_cnt[d], 1);
    }
}

__global__ void k_dis() {
    int i = blockIdx.x * 256 + threadIdx.x;
    if (i < NN) {
        float d = g_deg[i];
        g_dis[i] = (d > 0.0f) ? rsqrtf(d) : 0.0f;
    }
}

__global__ void k_scan() {
    __shared__ int wsum[32];
    __shared__ int sh_carry;
    int tid = threadIdx.x;
    int lane = tid & 31, wid = tid >> 5;
    if (tid == 0) sh_carry = 0;
    __syncthreads();
    for (int base = 0; base < NN; base += 1024) {
        int i = base + tid;
        int v = (i < NN) ? g_cnt[i] : 0;
        int inc = v;
#pragma unroll
        for (int off = 1; off < 32; off <<= 1) {
            int t = __shfl_up_sync(0xFFFFFFFFu, inc, off);
            if (lane >= off) inc += t;
        }
        if (lane == 31) wsum[wid] = inc;
        __syncthreads();
        if (wid == 0) {
            int wv = wsum[lane];
            int winc = wv;
#pragma unroll
            for (int off = 1; off < 32; off <<= 1) {
                int t = __shfl_up_sync(0xFFFFFFFFu, winc, off);
                if (lane >= off) winc += t;
            }
            wsum[lane] = winc - wv;
        }
        __syncthreads();
        int excl = sh_carry + wsum[wid] + inc - v;
        if (i < NN) { g_rp[i] = excl; g_cur[i] = excl; }
        __syncthreads();
        if (tid == 1023) sh_carry = excl + v;
        __syncthreads();
    }
    if (tid == 0) g_rp[NN] = sh_carry;
}

__global__ void k_fill(const int* __restrict__ src, const int* __restrict__ dst,
                       const float* __restrict__ ew) {
    int e = blockIdx.x * 256 + threadIdx.x;
    if (e < EE) {
        int s = src[e], d = dst[e];
        float w = (s == d) ? 0.0f : ew[e];
        float nw = -g_dis[s] * w * g_dis[d];
        int pos = atomicAdd(&g_cur[d], 1);
        g_col[pos] = s;
        g_val[pos] = nw;
    }
}

// ===================== converts =============================================
__global__ void k_cvtA(const float* __restrict__ in, __half* __restrict__ hi) {
    size_t i = (size_t)blockIdx.x * 256 + threadIdx.x;
    if (i < (size_t)NN * CC / 4) {
        float4 v = *(const float4*)(in + i * 4);
        __half2 h0 = __floats2half2_rn(v.x, v.y);
        __half2 h1 = __floats2half2_rn(v.z, v.w);
        *(uint2*)(hi + i * 4) = make_uint2(*(uint32_t*)&h0, *(uint32_t*)&h1);
    }
}

struct WPtrs { const float* w[6]; };
__global__ void k_cvtW(WPtrs wp, __half* __restrict__ wt) {
    __shared__ float ts[32][33];
    int kb = blockIdx.x * 32;
    int nb = blockIdx.y * 32;
    const float* W = wp.w[blockIdx.z];
    int c = threadIdx.x & 31, r8 = threadIdx.x >> 5;
#pragma unroll
    for (int i = 0; i < 4; i++) {
        int kr = r8 + i * 8;
        ts[kr][c] = W[(size_t)(kb + kr) * 1024 + nb + c];
    }
    __syncthreads();
    __half* bh = wt + (size_t)blockIdx.z * WSZ;
#pragma unroll
    for (int i = 0; i < 4; i++) {
        int nr = r8 + i * 8;
        bh[(size_t)(nb + nr) * 3072 + kb + c] = __float2half(ts[c][nr]);
    }
}

// ============ Laplacian apply: fp16 gather, fp32 accum, fp16 out ============
template <bool CHEB2>
__global__ void k_lap16(const __half* __restrict__ in,
                        const float* __restrict__ sub,
                        __half* __restrict__ out) {
    int node = blockIdx.x;
    int c4 = threadIdx.x;
    int s = g_rp[node], e = g_rp[node + 1];
    float a0 = 0.f, a1 = 0.f, a2 = 0.f, a3 = 0.f;
    for (int i = s; i < e; i++) {
        float w = __ldg(&g_val[i]);
        int   c = __ldg(&g_col[i]);
        uint2 hv = *(const uint2*)(in + (size_t)c * CC + c4 * 4);
        __half2 p0 = *reinterpret_cast<__half2*>(&hv.x);
        __half2 p1 = *reinterpret_cast<__half2*>(&hv.y);
        float2 f0 = __half22float2(p0);
        float2 f1 = __half22float2(p1);
        a0 += w * f0.x; a1 += w * f0.y; a2 += w * f1.x; a3 += w * f1.y;
    }
    if (CHEB2) {
        float4 sb = *(const float4*)(sub + (size_t)node * CC + c4 * 4);
        a0 = 2.f * a0 - sb.x; a1 = 2.f * a1 - sb.y;
        a2 = 2.f * a2 - sb.z; a3 = 2.f * a3 - sb.w;
    }
    __half2 o0 = __floats2half2_rn(a0, a1);
    __half2 o1 = __floats2half2_rn(a2, a3);
    *(uint2*)(out + (size_t)node * CC + c4 * 4) =
        make_uint2(*(uint32_t*)&o0, *(uint32_t*)&o1);
}

// ===================== merged pipelined MMA GEMM ============================
// CTA tile 128M x 128N, BK=64, 3-stage pipeline, 2 CTAs/SM, NSEG compile-time.
#define STAGE 32768u
#define OFF_B  16384u
#define GEMM_SMEM (3 * 32768)

struct SegPtrsH { const __half* a[6]; };
struct GJob {
    const __half* Wa; const __half* Wb;
    float* C;
    const float* b1; const float* b2;
    int epi;   // 1 Z, 2 R->H*R, 3 final mix
};
struct GParams {
    SegPtrsH sp;
    GJob job[2];
    const float* Hin; const float* Zin;
    __half* hr16; float* hr32;
    float* outp;
};

template <int NSEG>
__global__ __launch_bounds__(256, 2)
void k_gemmM(GParams gp) {
    extern __shared__ __align__(1024) char sm[];
    const uint32_t smb = smem_to_u32(sm);
    const int tid = threadIdx.x;
    const int m0 = blockIdx.y * 128;
    const int n0 = blockIdx.x * 128;
    const GJob jb = gp.job[blockIdx.z];
    constexpr int nst = NSEG * 16;

    const int warp = tid >> 5, lane = tid & 31;
    const int wm = (warp >> 1) * 32, wn = (warp & 1) * 64;
    const int lj = lane >> 3, lr = lane & 7;
    const uint32_t a_off = (uint32_t)(((lj & 1) * 8 + lr) * 128 + (lj >> 1) * 16);
    const uint32_t b_off = (uint32_t)(((lj >> 1) * 8 + lr) * 128 + (lj & 1) * 16);

    // ---- hoisted per-thread copy-offsets (stage-invariant) ----
    uint32_t smA[4], smB[4];         // swizzled smem offsets
    uint32_t gA[4];                  // row*1024 + cc*8 (elements)
    uint32_t gB[4];                  // (n0+row)*3072 + cc*8
    bool     vA[4];
#pragma unroll
    for (int t = 0; t < 4; t++) {
        int c = tid + t * 256;
        int row = c >> 3, cc = c & 7;
        smA[t] = SWZ((uint32_t)(row * 128 + cc * 16));
        smB[t] = OFF_B + smA[t];
        vA[t]  = (m0 + row) < NN;
        gA[t]  = (uint32_t)((m0 + row) * 1024 + cc * 8);
        gB[t]  = (uint32_t)((n0 + row) * 3072 + cc * 8);
    }

    float acc[2][8][4];
#pragma unroll
    for (int a = 0; a < 2; a++)
#pragma unroll
        for (int b = 0; b < 8; b++)
#pragma unroll
            for (int c = 0; c < 4; c++) acc[a][b][c] = 0.f;

    auto issue = [&](int st) {
        const int seg = st >> 4;
        const int k0 = (st & 15) * 64;
        const int wk = (seg % 3) * 1024 + k0;
        const uint32_t buf = smb + (uint32_t)(st % 3) * STAGE;
        const __half* ah = gp.sp.a[seg] + k0;
        const __half* wt = ((seg < 3) ? jb.Wa : jb.Wb) + wk;
#pragma unroll
        for (int t = 0; t < 4; t++)
            cpa16(buf + smA[t], ah + gA[t], vA[t]);
#pragma unroll
        for (int t = 0; t < 4; t++)
            cpa16(buf + smB[t], wt + gB[t], true);
    };

    issue(0);
    CP_COMMIT();
    issue(1);
    CP_COMMIT();

#pragma unroll 3
    for (int st = 0; st < nst; st++) {
        if (st + 2 < nst) {
            issue(st + 2);
            CP_COMMIT();
            CP_WAIT(2);
        } else if (st + 1 < nst) {
            CP_WAIT(1);
        } else {
            CP_WAIT(0);
        }
        __syncthreads();
        const uint32_t buf = smb + (uint32_t)(st % 3) * STAGE;

#pragma unroll
        for (int kk = 0; kk < 4; kk++) {
            const uint32_t kb = (uint32_t)(kk * 32);
            uint32_t ah[2][4];
#pragma unroll
            for (int mi = 0; mi < 2; mi++) {
                uint32_t ad = buf + SWZ((uint32_t)((wm + mi * 16) * 128) + kb + a_off);
                ldsm4(ah[mi], ad);
            }
#pragma unroll
            for (int g = 0; g < 4; g++) {
                uint32_t bd = buf + OFF_B +
                    SWZ((uint32_t)((wn + g * 16) * 128) + kb + b_off);
                uint32_t bh[4];
                ldsm4(bh, bd);
#pragma unroll
                for (int mi = 0; mi < 2; mi++) {
#pragma unroll
                    for (int f = 0; f < 2; f++)
                        mma_fp16(acc[mi][2 * g + f], ah[mi], bh + 2 * f);
                }
            }
        }
        __syncthreads();
    }

    // ---- fused epilogue ----
    const int gq = lane >> 2, tq = lane & 3;
    const int epi = jb.epi;
    float* C = jb.C;
#pragma unroll
    for (int mi = 0; mi < 2; mi++) {
#pragma unroll
        for (int hh = 0; hh < 2; hh++) {
            int r = m0 + wm + mi * 16 + gq + hh * 8;
            if (r >= NN) continue;
#pragma unroll
            for (int nf = 0; nf < 8; nf++) {
                int col = n0 + wn + nf * 8 + tq * 2;
                float v0 = acc[mi][nf][2 * hh];
                float v1 = acc[mi][nf][2 * hh + 1];
                size_t o = (size_t)r * 1024 + col;
                float2 b1 = *(const float2*)(jb.b1 + col);
                float2 b2 = *(const float2*)(jb.b2 + col);
                if (epi == 1) {
                    float z0 = sigm(v0 + b1.x + b2.x);
                    float z1 = sigm(v1 + b1.y + b2.y);
                    *(float2*)(C + o) = make_float2(z0, z1);
                } else if (epi == 2) {
                    float2 hv = *(const float2*)(gp.Hin + o);
                    float hr0 = hv.x * sigm(v0 + b1.x + b2.x);
                    float hr1 = hv.y * sigm(v1 + b1.y + b2.y);
                    *(float2*)(gp.hr32 + o) = make_float2(hr0, hr1);
                    __half2 h = __floats2half2_rn(hr0, hr1);
                    *(uint32_t*)(gp.hr16 + o) = *(uint32_t*)&h;
                } else {
                    float2 zv = *(const float2*)(gp.Zin + o);
                    float2 hv = *(const float2*)(gp.Hin + o);
                    float t0 = tanhf(v0 + b1.x + b2.x);
                    float t1 = tanhf(v1 + b1.y + b2.y);
                    float o0 = zv.x * hv.x + (1.f - zv.x) * t0;
                    float o1 = zv.y * hv.y + (1.f - zv.y) * t1;
                    *(float2*)(gp.outp + o) = make_float2(o0, o1);
                }
            }
        }
    }
}

// ===================== launch ===============================================
extern "C" void kernel_launch(void* const* d_in, const int* in_sizes, int n_in,
                              void* d_out, int out_size) {
    const float* x   = (const float*)d_in[0];
    const float* H   = (const float*)d_in[1];
    const int*   ei  = (const int*)d_in[2];
    const int*   src = ei;
    const int*   dst = ei + EE;
    const float* ew  = (const float*)d_in[3];
    const float* Wxz = (const float*)d_in[4];
    const float* bxz = (const float*)d_in[5];
    const float* Whz = (const float*)d_in[6];
    const float* bhz = (const float*)d_in[7];
    const float* Wxr = (const float*)d_in[8];
    const float* bxr = (const float*)d_in[9];
    const float* Whr = (const float*)d_in[10];
    const float* bhr = (const float*)d_in[11];
    const float* Wxh = (const float*)d_in[12];
    const float* bxh = (const float*)d_in[13];
    const float* Whh = (const float*)d_in[14];
    const float* bhh = (const float*)d_in[15];
    float* out = (float*)d_out;

    float *T2h, *Zp;
    cudaGetSymbolAddress((void**)&T2h, g_T2h);
    cudaGetSymbolAddress((void**)&Zp,  g_Zp);

    __half *hX, *h1X, *h2X, *hH, *h1H, *h2H, *hR, *h1R, *h2R, *Wt;
    cudaGetSymbolAddress((void**)&hX,  g_hX);
    cudaGetSymbolAddress((void**)&h1X, g_h1X);
    cudaGetSymbolAddress((void**)&h2X, g_h2X);
    cudaGetSymbolAddress((void**)&hH,  g_hH);
    cudaGetSymbolAddress((void**)&h1H, g_h1H);
    cudaGetSymbolAddress((void**)&h2H, g_h2H);
    cudaGetSymbolAddress((void**)&hR,  g_hR);
    cudaGetSymbolAddress((void**)&h1R, g_h1R);
    cudaGetSymbolAddress((void**)&h2R, g_h2R);
    cudaGetSymbolAddress((void**)&Wt,  g_Wt);

    cudaFuncSetAttribute(k_gemmM<6>,
        cudaFuncAttributeMaxDynamicSharedMemorySize, GEMM_SMEM);

    const int NB_N = (NN + 255) / 256;
    const int NB_E = (EE + 255) / 256;
    const int NB_F4 = (int)(((size_t)NN * CC / 4 + 255) / 256);
    const int MT = (NN + 127) / 128;         // 157 m-tiles

    // normalization + CSR
    k_zero<<<NB_N, 256>>>();
    k_deg <<<NB_E, 256>>>(src, dst, ew);
    k_dis <<<NB_N, 256>>>();
    k_scan<<<1, 1024>>>();
    k_fill<<<NB_E, 256>>>(src, dst, ew);

    // weight transpose + fp16 (order: Wxz, Whz, Wxr, Whr, Wxh, Whh)
    WPtrs wp;
    wp.w[0] = Wxz; wp.w[1] = Whz; wp.w[2] = Wxr;
    wp.w[3] = Whr; wp.w[4] = Wxh; wp.w[5] = Whh;
    k_cvtW<<<dim3(96, 32, 6), 256>>>(wp, Wt);

    // x, H fp16 converts
    k_cvtA<<<NB_F4, 256>>>(x, hX);
    k_cvtA<<<NB_F4, 256>>>(H, hH);

    // Chebyshev recursions (fp16 gather, fp32 accum, fp16 out)
    k_lap16<false><<<NN, 256>>>(hX,  nullptr, h1X);
    k_lap16<true> <<<NN, 256>>>(h1X, x,       h2X);
    k_lap16<false><<<NN, 256>>>(hH,  nullptr, h1H);
    k_lap16<true> <<<NN, 256>>>(h1H, H,       h2H);

    // merged Z / R GEMM (blockIdx.z = job; both 6-seg = balanced)
    GParams gzr;
    gzr.sp.a[0] = hX;  gzr.sp.a[1] = h1X; gzr.sp.a[2] = h2X;
    gzr.sp.a[3] = hH;  gzr.sp.a[4] = h1H; gzr.sp.a[5] = h2H;
    gzr.Hin = H; gzr.Zin = nullptr;
    gzr.hr16 = hR; gzr.hr32 = T2h; gzr.outp = nullptr;
    gzr.job[0] = {Wt, Wt + WSZ, Zp, bxz, bhz, 1};                  // Z
    gzr.job[1] = {Wt + 2 * WSZ, Wt + 3 * WSZ, nullptr, bxr, bhr, 2}; // R->HR
    k_gemmM<6><<<dim3(8, MT, 2), 256, GEMM_SMEM>>>(gzr);

    // Chebyshev recursion for H*R
    k_lap16<false><<<NN, 256>>>(hR,  nullptr, h1R);
    k_lap16<true> <<<NN, 256>>>(h1R, T2h,     h2R);

    // final 6-seg GEMM: out = Z*H + (1-Z)*tanh(Xcat@Wxh + HRcat@Whh + b)
    GParams gpf;
    gpf.sp.a[0] = hX;  gpf.sp.a[1] = h1X; gpf.sp.a[2] = h2X;
    gpf.sp.a[3] = hR;  gpf.sp.a[4] = h1R; gpf.sp.a[5] = h2R;
    gpf.Hin = H; gpf.Zin = Zp;
    gpf.hr16 = nullptr; gpf.hr32 = nullptr; gpf.outp = out;
    gpf.job[0] = {Wt + 4 * WSZ, Wt + 5 * WSZ, nullptr, bxh, bhh, 3};
    gpf.job[1] = gpf.job[0];
    k_gemmM<6><<<dim3(8, MT, 1), 256, GEMM_SMEM>>>(gpf);
}